// round 1
// baseline (speedup 1.0000x reference)
#include <cuda_runtime.h>
#include <math.h>

#define DIMK 64
#define NN 16
#define BATCH 4096
#define NREL 33
#define IPB 8
#define NT 256
#define GRID (BATCH / IPB)

struct Smem {
    float W0[DIMK * DIMK];
    float W1[DIMK * DIMK];
    float b0[DIMK];
    float b1[DIMK];
    float userv[DIMK];
    float urel[NREL + 3];
    int   e1[NN];
    int   r1[NN];
    float sc0[NN];
    float attn0[NN];
    int   e2[NN * NN];
    float s2[NN * NN];
    float attn[NN * NN];
    float e0v[DIMK];
    float e1v[NN * DIMK];
    float xbuf[NN * DIMK];
    float h1[NN * DIMK];
    float out0[DIMK];
    float outf[DIMK];
};

__device__ __forceinline__ float fsigmoid(float x) {
    return __fdividef(1.0f, 1.0f + __expf(-x));
}

__global__ __launch_bounds__(NT, 4)
void kgnn_kernel(const int* __restrict__ u, const int* __restrict__ v,
                 const int* __restrict__ adj, const int* __restrict__ rel_adj,
                 const float* __restrict__ usr_emb, const float* __restrict__ ent_emb,
                 const float* __restrict__ rel_emb,
                 const float* __restrict__ W0g, const float* __restrict__ b0g,
                 const float* __restrict__ W1g, const float* __restrict__ b1g,
                 float* __restrict__ out)
{
    extern __shared__ char smem_raw[];
    Smem& s = *reinterpret_cast<Smem*>(smem_raw);
    const int tid = threadIdx.x;

    // Load weights once per block (amortized over IPB items)
    {
        const float4* w0 = reinterpret_cast<const float4*>(W0g);
        const float4* w1 = reinterpret_cast<const float4*>(W1g);
        float4* w0s = reinterpret_cast<float4*>(s.W0);
        float4* w1s = reinterpret_cast<float4*>(s.W1);
        #pragma unroll
        for (int i = tid; i < DIMK * DIMK / 4; i += NT) { w0s[i] = w0[i]; w1s[i] = w1[i]; }
        if (tid < DIMK) { s.b0[tid] = b0g[tid]; s.b1[tid] = b1g[tid]; }
    }

    for (int it = 0; it < IPB; ++it) {
        const int item = blockIdx.x * IPB + it;
        __syncthreads();  // weights ready (it=0) / previous item fully consumed

        // ---- Phase 1: scalar + vector loads ----
        const int vv = __ldg(v + item);
        if (tid < DIMK) {
            s.userv[tid] = usr_emb[__ldg(u + item) * DIMK + tid];
        } else if (tid < 2 * DIMK) {
            s.e0v[tid - DIMK] = ent_emb[vv * DIMK + (tid - DIMK)];
        } else if (tid < 2 * DIMK + NN) {
            s.e1[tid - 2 * DIMK] = adj[vv * NN + (tid - 2 * DIMK)];
        } else if (tid < 2 * DIMK + 2 * NN) {
            s.r1[tid - 2 * DIMK - NN] = rel_adj[vv * NN + (tid - 2 * DIMK - NN)];
        }
        __syncthreads();

        // ---- Phase 2: urel[r] = user . rel_emb[r]  (scores depend only on rel id) ----
        {
            const int warp = tid >> 5, lane = tid & 31;
            for (int r = warp; r < NREL; r += 8) {
                float p = s.userv[lane] * rel_emb[r * DIMK + lane]
                        + s.userv[lane + 32] * rel_emb[r * DIMK + lane + 32];
                #pragma unroll
                for (int off = 16; off > 0; off >>= 1)
                    p += __shfl_xor_sync(0xffffffffu, p, off);
                if (lane == 0) s.urel[r] = p;
            }
        }
        __syncthreads();

        // ---- Phase 3: hop-2 indices+scores, hop-1 vectors ----
        {
            const int m = tid >> 4, n = tid & 15;
            const int e1m = s.e1[m];
            s.e2[tid] = adj[e1m * NN + n];
            s.s2[tid] = s.urel[rel_adj[e1m * NN + n]];
            if (tid < NN) s.sc0[tid] = s.urel[s.r1[tid]];
            #pragma unroll
            for (int k = 0; k < 4; ++k) {
                const int lin = tid + k * NT;
                const int mm = lin >> 6, d = lin & 63;
                s.e1v[lin] = ent_emb[s.e1[mm] * DIMK + d];
            }
        }
        __syncthreads();

        // ---- Phase 4: softmax (hop1 rows + hop0 row; hop0 attn reused in iter1) ----
        {
            const int m = tid >> 4, n = tid & 15;
            const float* row = s.s2 + m * NN;
            float mx = row[0];
            #pragma unroll
            for (int j = 1; j < NN; ++j) mx = fmaxf(mx, row[j]);
            float sum = 0.f, es = 0.f;
            #pragma unroll
            for (int j = 0; j < NN; ++j) {
                float e = __expf(row[j] - mx);
                sum += e;
                if (j == n) es = e;
            }
            s.attn[tid] = __fdividef(es, sum);
            if (tid < NN) {
                float m0 = s.sc0[0];
                #pragma unroll
                for (int j = 1; j < NN; ++j) m0 = fmaxf(m0, s.sc0[j]);
                float sum0 = 0.f;
                #pragma unroll
                for (int j = 0; j < NN; ++j) sum0 += __expf(s.sc0[j] - m0);
                s.attn0[tid] = __fdividef(__expf(s.sc0[tid] - m0), sum0);
            }
        }
        __syncthreads();

        // ---- Phase 5: hop1 x = sv + sum_n attn*ent_emb[e2]  (streamed gather) ----
        {
            const int d = tid & 63, g = tid >> 6;
            #pragma unroll
            for (int mi = 0; mi < 4; ++mi) {
                const int m = g * 4 + mi;
                const int* e2row = s.e2 + m * NN;
                const float* arow = s.attn + m * NN;
                float acc = s.e1v[m * DIMK + d];
                #pragma unroll
                for (int n = 0; n < NN; ++n)
                    acc = fmaf(arow[n], __ldg(ent_emb + e2row[n] * DIMK + d), acc);
                s.xbuf[m * DIMK + d] = acc;
            }
        }
        __syncthreads();

        // ---- Phase 6: h1 = sigmoid(x @ W0 + b0)  (float4 W reads) ----
        {
            const int m = tid >> 4, c = tid & 15;
            const float4* w4 = reinterpret_cast<const float4*>(s.W0);
            const float* x = s.xbuf + m * DIMK;
            float4 acc = reinterpret_cast<const float4*>(s.b0)[c];
            #pragma unroll
            for (int k = 0; k < DIMK; ++k) {
                const float xv = x[k];
                const float4 w = w4[k * 16 + c];
                acc.x = fmaf(xv, w.x, acc.x);
                acc.y = fmaf(xv, w.y, acc.y);
                acc.z = fmaf(xv, w.z, acc.z);
                acc.w = fmaf(xv, w.w, acc.w);
            }
            acc.x = fsigmoid(acc.x); acc.y = fsigmoid(acc.y);
            acc.z = fsigmoid(acc.z); acc.w = fsigmoid(acc.w);
            reinterpret_cast<float4*>(s.h1 + m * DIMK)[c] = acc;
        }
        __syncthreads();

        // ---- Phase 7: hop0 iter0 ----
        if (tid < DIMK) {
            float acc = s.e0v[tid];
            #pragma unroll
            for (int n = 0; n < NN; ++n)
                acc = fmaf(s.attn0[n], s.e1v[n * DIMK + tid], acc);
            s.xbuf[tid] = acc;
        }
        __syncthreads();
        if (tid < 16) {
            const float4* w4 = reinterpret_cast<const float4*>(s.W0);
            float4 acc = reinterpret_cast<const float4*>(s.b0)[tid];
            #pragma unroll
            for (int k = 0; k < DIMK; ++k) {
                const float xv = s.xbuf[k];
                const float4 w = w4[k * 16 + tid];
                acc.x = fmaf(xv, w.x, acc.x);
                acc.y = fmaf(xv, w.y, acc.y);
                acc.z = fmaf(xv, w.z, acc.z);
                acc.w = fmaf(xv, w.w, acc.w);
            }
            acc.x = fsigmoid(acc.x); acc.y = fsigmoid(acc.y);
            acc.z = fsigmoid(acc.z); acc.w = fsigmoid(acc.w);
            reinterpret_cast<float4*>(s.out0)[tid] = acc;
        }
        __syncthreads();

        // ---- Phase 8: iter1 hop0 (attn0 reused; neighbors = h1) ----
        if (tid < DIMK) {
            float acc = s.out0[tid];
            #pragma unroll
            for (int n = 0; n < NN; ++n)
                acc = fmaf(s.attn0[n], s.h1[n * DIMK + tid], acc);
            s.xbuf[tid] = acc;
        }
        __syncthreads();
        if (tid < 16) {
            const float4* w4 = reinterpret_cast<const float4*>(s.W1);
            float4 acc = reinterpret_cast<const float4*>(s.b1)[tid];
            #pragma unroll
            for (int k = 0; k < DIMK; ++k) {
                const float xv = s.xbuf[k];
                const float4 w = w4[k * 16 + tid];
                acc.x = fmaf(xv, w.x, acc.x);
                acc.y = fmaf(xv, w.y, acc.y);
                acc.z = fmaf(xv, w.z, acc.z);
                acc.w = fmaf(xv, w.w, acc.w);
            }
            acc.x = tanhf(acc.x); acc.y = tanhf(acc.y);
            acc.z = tanhf(acc.z); acc.w = tanhf(acc.w);
            reinterpret_cast<float4*>(s.outf)[tid] = acc;
        }
        __syncthreads();

        // ---- Final: sigmoid(user . item) ----
        if (tid < 32) {
            float p = s.userv[tid] * s.outf[tid] + s.userv[tid + 32] * s.outf[tid + 32];
            #pragma unroll
            for (int off = 16; off > 0; off >>= 1)
                p += __shfl_xor_sync(0xffffffffu, p, off);
            if (tid == 0) out[item] = fsigmoid(p);
        }
    }
}

extern "C" void kernel_launch(void* const* d_in, const int* in_sizes, int n_in,
                              void* d_out, int out_size) {
    const int*   u       = (const int*)d_in[0];
    const int*   v       = (const int*)d_in[1];
    const int*   adj     = (const int*)d_in[2];
    const int*   rel_adj = (const int*)d_in[3];
    const float* usr_emb = (const float*)d_in[4];
    const float* ent_emb = (const float*)d_in[5];
    const float* rel_emb = (const float*)d_in[6];
    const float* W0      = (const float*)d_in[7];
    const float* b0      = (const float*)d_in[8];
    const float* W1      = (const float*)d_in[9];
    const float* b1      = (const float*)d_in[10];
    float* out = (float*)d_out;

    const int smem = (int)sizeof(Smem);
    cudaFuncSetAttribute(kgnn_kernel, cudaFuncAttributeMaxDynamicSharedMemorySize, smem);
    kgnn_kernel<<<GRID, NT, smem>>>(u, v, adj, rel_adj, usr_emb, ent_emb, rel_emb,
                                    W0, b0, W1, b1, out);
}

// round 2
// speedup vs baseline: 1.0557x; 1.0557x over previous
#include <cuda_runtime.h>
#include <math.h>

#define DIMK 64
#define NN 16
#define BATCH 4096
#define NRELS 33
#define IPB 2
#define NT 256
#define GRID (BATCH / IPB)

struct Smem {
    float W0[DIMK * DIMK];     // 16 KB (W1 stays in L2)
    float b0[DIMK];
    float b1[DIMK];
    float userv[DIMK];
    float e0v[DIMK];
    float urel[NRELS + 3];
    int   e1[NN];
    int   r1[NN];
    float attn0[NN];
    int   e2[NN * NN];
    int   r2[NN * NN];
    float attn[NN * NN];
    float e1v[NN * DIMK];      // 4 KB
    float xbuf[NN * DIMK];     // 4 KB
    float h1[NN * DIMK];       // 4 KB
    float x0[DIMK];
    float x1[DIMK];
    float out0[DIMK];
    float outf[DIMK];
};

__device__ __forceinline__ float fsigmoid(float x) {
    return __fdividef(1.0f, 1.0f + __expf(-x));
}

__global__ __launch_bounds__(NT, 6)
void kgnn_kernel(const int* __restrict__ u, const int* __restrict__ v,
                 const int* __restrict__ adj, const int* __restrict__ rel_adj,
                 const float* __restrict__ usr_emb, const float* __restrict__ ent_emb,
                 const float* __restrict__ rel_emb,
                 const float* __restrict__ W0g, const float* __restrict__ b0g,
                 const float* __restrict__ W1g, const float* __restrict__ b1g,
                 float* __restrict__ out)
{
    extern __shared__ char smem_raw[];
    Smem& s = *reinterpret_cast<Smem*>(smem_raw);
    const int tid = threadIdx.x;

    // Preamble: W0 + biases (amortized over IPB items)
    {
        const float4* w0 = reinterpret_cast<const float4*>(W0g);
        float4* w0s = reinterpret_cast<float4*>(s.W0);
        #pragma unroll
        for (int i = tid; i < DIMK * DIMK / 4; i += NT) w0s[i] = w0[i];
        if (tid < DIMK) { s.b0[tid] = b0g[tid]; s.b1[tid] = b1g[tid]; }
    }

    for (int it = 0; it < IPB; ++it) {
        const int item = blockIdx.x * IPB + it;
        __syncthreads();   // weights ready / previous item fully consumed

        // ---- P1: root loads ----
        const int vv = __ldg(v + item);
        if (tid < DIMK) {
            s.userv[tid] = usr_emb[__ldg(u + item) * DIMK + tid];
        } else if (tid < 2 * DIMK) {
            s.e0v[tid - DIMK] = ent_emb[vv * DIMK + (tid - DIMK)];
        } else if (tid < 2 * DIMK + NN) {
            s.e1[tid - 2 * DIMK] = adj[vv * NN + (tid - 2 * DIMK)];
        } else if (tid < 2 * DIMK + 2 * NN) {
            s.r1[tid - 2 * DIMK - NN] = rel_adj[vv * NN + (tid - 2 * DIMK - NN)];
        }
        __syncthreads();

        // ---- P2: hop-2 index gather + hop-1 vectors + urel (fused) ----
        {
            const int m = tid >> 4, n = tid & 15;
            const int e1m = s.e1[m];
            s.e2[tid] = adj[e1m * NN + n];
            s.r2[tid] = rel_adj[e1m * NN + n];
            #pragma unroll
            for (int k = 0; k < 4; ++k) {
                const int lin = tid + k * NT;
                s.e1v[lin] = ent_emb[s.e1[lin >> 6] * DIMK + (lin & 63)];
            }
            const int warp = tid >> 5, lane = tid & 31;
            for (int r = warp; r < NRELS; r += 8) {
                float p = s.userv[lane] * rel_emb[r * DIMK + lane]
                        + s.userv[lane + 32] * rel_emb[r * DIMK + lane + 32];
                #pragma unroll
                for (int off = 16; off > 0; off >>= 1)
                    p += __shfl_xor_sync(0xffffffffu, p, off);
                if (lane == 0) s.urel[r] = p;
            }
        }
        __syncthreads();

        // ---- P3: softmax (scores looked up from urel by rel id) ----
        {
            const int m = tid >> 4, n = tid & 15;
            const int* rrow = s.r2 + m * NN;
            float mx = -1e30f;
            #pragma unroll
            for (int j = 0; j < NN; ++j) mx = fmaxf(mx, s.urel[rrow[j]]);
            float sum = 0.f, mine = 0.f;
            #pragma unroll
            for (int j = 0; j < NN; ++j) {
                float e = __expf(s.urel[rrow[j]] - mx);
                sum += e;
                if (j == n) mine = e;
            }
            s.attn[tid] = __fdividef(mine, sum);
            if (tid < NN) {
                float m0 = -1e30f;
                #pragma unroll
                for (int j = 0; j < NN; ++j) m0 = fmaxf(m0, s.urel[s.r1[j]]);
                float s0 = 0.f;
                #pragma unroll
                for (int j = 0; j < NN; ++j) s0 += __expf(s.urel[s.r1[j]] - m0);
                s.attn0[tid] = __fdividef(__expf(s.urel[s.r1[tid]] - m0), s0);
            }
        }
        __syncthreads();

        // ---- P4: hop-1 aggregation (streamed gather) + hop-0 aggregation ----
        {
            const int d = tid & 63, g = tid >> 6;
            #pragma unroll
            for (int mi = 0; mi < 4; ++mi) {
                const int m = g * 4 + mi;
                const int* e2row = s.e2 + m * NN;
                const float* arow = s.attn + m * NN;
                float acc = s.e1v[m * DIMK + d];
                #pragma unroll
                for (int n = 0; n < NN; ++n)
                    acc = fmaf(arow[n], __ldg(ent_emb + e2row[n] * DIMK + d), acc);
                s.xbuf[m * DIMK + d] = acc;
            }
            if (tid < DIMK) {
                float a = s.e0v[tid];
                #pragma unroll
                for (int n = 0; n < NN; ++n)
                    a = fmaf(s.attn0[n], s.e1v[n * DIMK + tid], a);
                s.x0[tid] = a;
            }
        }
        __syncthreads();

        // ---- P5: h1 = sigmoid(x@W0+b0) [16 rows] + out0 = sigmoid(x0@W0+b0) ----
        {
            const int m = tid >> 4, c = tid & 15;
            const float4* w4 = reinterpret_cast<const float4*>(s.W0);
            const float* x = s.xbuf + m * DIMK;
            float4 acc = reinterpret_cast<const float4*>(s.b0)[c];
            #pragma unroll
            for (int k = 0; k < DIMK; ++k) {
                const float xv = x[k];
                const float4 w = w4[k * 16 + c];
                acc.x = fmaf(xv, w.x, acc.x);
                acc.y = fmaf(xv, w.y, acc.y);
                acc.z = fmaf(xv, w.z, acc.z);
                acc.w = fmaf(xv, w.w, acc.w);
            }
            acc.x = fsigmoid(acc.x); acc.y = fsigmoid(acc.y);
            acc.z = fsigmoid(acc.z); acc.w = fsigmoid(acc.w);
            reinterpret_cast<float4*>(s.h1 + m * DIMK)[c] = acc;

            // hop-0 GEMM, k-split x4 (16-iter chain), shfl reduce
            const int c6 = tid >> 2, kq = tid & 3;
            float a0 = 0.f;
            #pragma unroll
            for (int kk = 0; kk < 16; ++kk) {
                const int k = kq * 16 + kk;
                a0 = fmaf(s.x0[k], s.W0[k * DIMK + c6], a0);
            }
            a0 += __shfl_xor_sync(0xffffffffu, a0, 1);
            a0 += __shfl_xor_sync(0xffffffffu, a0, 2);
            if (kq == 0) s.out0[c6] = fsigmoid(a0 + s.b0[c6]);
        }
        __syncthreads();

        // ---- P6: hop-0 iter-1 aggregation (attn0 reused, neighbors = h1) ----
        if (tid < DIMK) {
            float a = s.out0[tid];
            #pragma unroll
            for (int n = 0; n < NN; ++n)
                a = fmaf(s.attn0[n], s.h1[n * DIMK + tid], a);
            s.x1[tid] = a;
        }
        __syncthreads();

        // ---- P7: final GEMM (W1 from L2), k-split x4, tanh ----
        {
            const int c6 = tid >> 2, kq = tid & 3;
            float a1 = 0.f;
            #pragma unroll
            for (int kk = 0; kk < 16; ++kk) {
                const int k = kq * 16 + kk;
                a1 = fmaf(s.x1[k], __ldg(W1g + k * DIMK + c6), a1);
            }
            a1 += __shfl_xor_sync(0xffffffffu, a1, 1);
            a1 += __shfl_xor_sync(0xffffffffu, a1, 2);
            if (kq == 0) s.outf[c6] = tanhf(a1 + s.b1[c6]);
        }
        __syncthreads();

        // ---- P8: final sigmoid(user . item) ----
        if (tid < 32) {
            float p = s.userv[tid] * s.outf[tid] + s.userv[tid + 32] * s.outf[tid + 32];
            #pragma unroll
            for (int off = 16; off > 0; off >>= 1)
                p += __shfl_xor_sync(0xffffffffu, p, off);
            if (tid == 0) out[item] = fsigmoid(p);
        }
    }
}

extern "C" void kernel_launch(void* const* d_in, const int* in_sizes, int n_in,
                              void* d_out, int out_size) {
    const int*   u       = (const int*)d_in[0];
    const int*   v       = (const int*)d_in[1];
    const int*   adj     = (const int*)d_in[2];
    const int*   rel_adj = (const int*)d_in[3];
    const float* usr_emb = (const float*)d_in[4];
    const float* ent_emb = (const float*)d_in[5];
    const float* rel_emb = (const float*)d_in[6];
    const float* W0      = (const float*)d_in[7];
    const float* b0      = (const float*)d_in[8];
    const float* W1      = (const float*)d_in[9];
    const float* b1      = (const float*)d_in[10];
    float* outp = (float*)d_out;

    const int smem = (int)sizeof(Smem);
    cudaFuncSetAttribute(kgnn_kernel, cudaFuncAttributeMaxDynamicSharedMemorySize, smem);
    kgnn_kernel<<<GRID, NT, smem>>>(u, v, adj, rel_adj, usr_emb, ent_emb, rel_emb,
                                    W0, b0, W1, b1, outp);
}

// round 3
// speedup vs baseline: 1.0881x; 1.0307x over previous
#include <cuda_runtime.h>
#include <math.h>

#define DIMK 64
#define NN 16
#define BATCH 4096
#define NRELS 33
#define IPB 2
#define NT 256
#define GRID (BATCH / IPB)

struct Smem {
    // float4-accessed arrays first (keep 16B alignment)
    float e1v[NN * DIMK];     // 4 KB
    float xbuf[NN * DIMK];    // 4 KB
    float h1[NN * DIMK];      // 4 KB
    float userv[DIMK];
    float e0v[DIMK];
    float x0[DIMK];
    float x1[DIMK];
    float out0[DIMK];
    float outf[DIMK];
    float b0[DIMK];
    float b1[DIMK];
    // scalar-accessed
    float urel[NRELS + 3];
    float attn[NN * NN];
    float attn0[NN];
    int   e2[NN * NN];
    int   r2[NN * NN];
    int   r1[NN];
};

__device__ __forceinline__ float fsigmoid(float x) {
    return __fdividef(1.0f, 1.0f + __expf(-x));
}

__global__ __launch_bounds__(NT, 6)
void kgnn_kernel(const int* __restrict__ u, const int* __restrict__ v,
                 const int* __restrict__ adj, const int* __restrict__ rel_adj,
                 const float* __restrict__ usr_emb, const float* __restrict__ ent_emb,
                 const float* __restrict__ rel_emb,
                 const float* __restrict__ W0g, const float* __restrict__ b0g,
                 const float* __restrict__ W1g, const float* __restrict__ b1g,
                 float* __restrict__ out)
{
    extern __shared__ char smem_raw[];
    Smem& s = *reinterpret_cast<Smem*>(smem_raw);
    const int tid  = threadIdx.x;
    const int lane = tid & 31;
    const int warp = tid >> 5;
    const int c    = warp * 8 + (lane & 7);   // output column 0..63
    const int kh   = lane >> 3;               // k-quarter 0..3
    const int kbase = kh * 16;

    const float4* ent4 = reinterpret_cast<const float4*>(ent_emb);

    // W0 column-slice in registers, once per CTA
    float Wreg[16];
    #pragma unroll
    for (int kk = 0; kk < 16; ++kk)
        Wreg[kk] = __ldg(W0g + (kbase + kk) * DIMK + c);
    if (tid < DIMK) { s.b0[tid] = b0g[tid]; s.b1[tid] = b1g[tid]; }

    for (int it = 0; it < IPB; ++it) {
        const int item = blockIdx.x * IPB + it;
        __syncthreads();   // biases ready / previous item fully consumed

        // ---- P1: root loads + hop indices + e1v gather + urel (fused) ----
        const int vv = __ldg(v + item);
        const int uu = __ldg(u + item);
        {
            const int m = tid >> 4, n = tid & 15;
            const int e1m = __ldg(adj + vv * NN + m);   // broadcast row, L1-cheap
            s.e2[tid] = __ldg(adj + e1m * NN + n);
            s.r2[tid] = __ldg(rel_adj + e1m * NN + n);
            reinterpret_cast<float4*>(s.e1v)[tid] = __ldg(ent4 + e1m * 16 + n);
            if (tid < 16) {
                s.r1[tid] = __ldg(rel_adj + vv * NN + tid);
                reinterpret_cast<float4*>(s.userv)[tid] = __ldg(
                    reinterpret_cast<const float4*>(usr_emb) + uu * 16 + tid);
            } else if (tid < 32) {
                reinterpret_cast<float4*>(s.e0v)[tid - 16] = __ldg(ent4 + vv * 16 + (tid - 16));
            }
            // urel[r] = user . rel_emb[r]  (direct from global; L1-cached)
            for (int r = warp; r < NRELS; r += 8) {
                float p = __ldg(usr_emb + uu * DIMK + lane) * __ldg(rel_emb + r * DIMK + lane)
                        + __ldg(usr_emb + uu * DIMK + lane + 32) * __ldg(rel_emb + r * DIMK + lane + 32);
                #pragma unroll
                for (int off = 16; off > 0; off >>= 1)
                    p += __shfl_xor_sync(0xffffffffu, p, off);
                if (lane == 0) s.urel[r] = p;
            }
        }
        __syncthreads();

        // ---- P2: softmax (scores = urel[rel id]) ----
        {
            const int m = tid >> 4, n = tid & 15;
            const int* rrow = s.r2 + m * NN;
            float mx = -1e30f;
            #pragma unroll
            for (int j = 0; j < NN; ++j) mx = fmaxf(mx, s.urel[rrow[j]]);
            float sum = 0.f, mine = 0.f;
            #pragma unroll
            for (int j = 0; j < NN; ++j) {
                float e = __expf(s.urel[rrow[j]] - mx);
                sum += e;
                if (j == n) mine = e;
            }
            s.attn[tid] = __fdividef(mine, sum);
            if (tid < NN) {
                float m0 = -1e30f;
                #pragma unroll
                for (int j = 0; j < NN; ++j) m0 = fmaxf(m0, s.urel[s.r1[j]]);
                float s0 = 0.f;
                #pragma unroll
                for (int j = 0; j < NN; ++j) s0 += __expf(s.urel[s.r1[j]] - m0);
                s.attn0[tid] = __fdividef(__expf(s.urel[s.r1[tid]] - m0), s0);
            }
        }
        __syncthreads();

        // ---- P3: hop-1 aggregation (float4 streamed gather) + hop-0 agg ----
        {
            const int m  = warp * 2 + (lane >> 4);
            const int l4 = lane & 15;
            const int*   e2row = s.e2  + m * NN;
            const float* arow  = s.attn + m * NN;
            float4 acc = reinterpret_cast<const float4*>(s.e1v + m * DIMK)[l4];
            #pragma unroll
            for (int n = 0; n < NN; ++n) {
                const float4 vv4 = __ldg(ent4 + e2row[n] * 16 + l4);
                const float  an  = arow[n];
                acc.x = fmaf(an, vv4.x, acc.x);
                acc.y = fmaf(an, vv4.y, acc.y);
                acc.z = fmaf(an, vv4.z, acc.z);
                acc.w = fmaf(an, vv4.w, acc.w);
            }
            reinterpret_cast<float4*>(s.xbuf + m * DIMK)[l4] = acc;

            if (tid < 16) {   // hop-0: x0 = e0v + sum attn0 * e1v
                float4 a0 = reinterpret_cast<const float4*>(s.e0v)[tid];
                #pragma unroll
                for (int n = 0; n < NN; ++n) {
                    const float4 ev = reinterpret_cast<const float4*>(s.e1v + n * DIMK)[tid];
                    const float  an = s.attn0[n];
                    a0.x = fmaf(an, ev.x, a0.x);
                    a0.y = fmaf(an, ev.y, a0.y);
                    a0.z = fmaf(an, ev.z, a0.z);
                    a0.w = fmaf(an, ev.w, a0.w);
                }
                reinterpret_cast<float4*>(s.x0)[tid] = a0;
            }
        }
        __syncthreads();

        // ---- P4: GEMM, W0 in registers, in-warp k-reduction ----
        {
            #pragma unroll
            for (int r0 = 0; r0 < NN; r0 += 4) {
                float a[4] = {0.f, 0.f, 0.f, 0.f};
                #pragma unroll
                for (int q = 0; q < 4; ++q) {
                    #pragma unroll
                    for (int rr = 0; rr < 4; ++rr) {
                        const float4 xv = *reinterpret_cast<const float4*>(
                            s.xbuf + (r0 + rr) * DIMK + kbase + q * 4);
                        a[rr] = fmaf(xv.x, Wreg[q * 4 + 0], a[rr]);
                        a[rr] = fmaf(xv.y, Wreg[q * 4 + 1], a[rr]);
                        a[rr] = fmaf(xv.z, Wreg[q * 4 + 2], a[rr]);
                        a[rr] = fmaf(xv.w, Wreg[q * 4 + 3], a[rr]);
                    }
                }
                #pragma unroll
                for (int rr = 0; rr < 4; ++rr) {
                    float t = a[rr];
                    t += __shfl_xor_sync(0xffffffffu, t, 8);
                    t += __shfl_xor_sync(0xffffffffu, t, 16);
                    if (kh == 0) s.h1[(r0 + rr) * DIMK + c] = fsigmoid(t + s.b0[c]);
                }
            }
            // row 16: x0 @ W0 -> out0
            float a16 = 0.f;
            #pragma unroll
            for (int q = 0; q < 4; ++q) {
                const float4 xv = *reinterpret_cast<const float4*>(s.x0 + kbase + q * 4);
                a16 = fmaf(xv.x, Wreg[q * 4 + 0], a16);
                a16 = fmaf(xv.y, Wreg[q * 4 + 1], a16);
                a16 = fmaf(xv.z, Wreg[q * 4 + 2], a16);
                a16 = fmaf(xv.w, Wreg[q * 4 + 3], a16);
            }
            a16 += __shfl_xor_sync(0xffffffffu, a16, 8);
            a16 += __shfl_xor_sync(0xffffffffu, a16, 16);
            if (kh == 0) s.out0[c] = fsigmoid(a16 + s.b0[c]);
        }
        __syncthreads();

        // ---- P5: iter-1 hop-0 aggregation (attn0 reused, neighbors = h1) ----
        if (tid < DIMK) {
            float a = s.out0[tid];
            #pragma unroll
            for (int n = 0; n < NN; ++n)
                a = fmaf(s.attn0[n], s.h1[n * DIMK + tid], a);
            s.x1[tid] = a;
        }
        __syncthreads();

        // ---- P6: final GEMM (W1 via L1/L2), same reduction ----
        {
            float acc = 0.f;
            #pragma unroll
            for (int kk = 0; kk < 16; ++kk) {
                const int k = kbase + kk;
                acc = fmaf(s.x1[k], __ldg(W1g + k * DIMK + c), acc);
            }
            acc += __shfl_xor_sync(0xffffffffu, acc, 8);
            acc += __shfl_xor_sync(0xffffffffu, acc, 16);
            if (kh == 0) s.outf[c] = tanhf(acc + s.b1[c]);
        }
        __syncthreads();

        // ---- P7: sigmoid(user . item) ----
        if (tid < 32) {
            float p = s.userv[tid] * s.outf[tid] + s.userv[tid + 32] * s.outf[tid + 32];
            #pragma unroll
            for (int off = 16; off > 0; off >>= 1)
                p += __shfl_xor_sync(0xffffffffu, p, off);
            if (tid == 0) out[item] = fsigmoid(p);
        }
    }
}

extern "C" void kernel_launch(void* const* d_in, const int* in_sizes, int n_in,
                              void* d_out, int out_size) {
    const int*   u       = (const int*)d_in[0];
    const int*   v       = (const int*)d_in[1];
    const int*   adj     = (const int*)d_in[2];
    const int*   rel_adj = (const int*)d_in[3];
    const float* usr_emb = (const float*)d_in[4];
    const float* ent_emb = (const float*)d_in[5];
    const float* rel_emb = (const float*)d_in[6];
    const float* W0      = (const float*)d_in[7];
    const float* b0      = (const float*)d_in[8];
    const float* W1      = (const float*)d_in[9];
    const float* b1      = (const float*)d_in[10];
    float* outp = (float*)d_out;

    const int smem = (int)sizeof(Smem);
    cudaFuncSetAttribute(kgnn_kernel, cudaFuncAttributeMaxDynamicSharedMemorySize, smem);
    kgnn_kernel<<<GRID, NT, smem>>>(u, v, adj, rel_adj, usr_emb, ent_emb, rel_emb,
                                    W0, b0, W1, b1, outp);
}

// round 4
// speedup vs baseline: 1.2052x; 1.1077x over previous
#include <cuda_runtime.h>
#include <math.h>

#define DIMK 64
#define NN 16
#define BATCH 4096
#define NRELS 33
#define IPB 2
#define NT 256
#define GRID (BATCH / IPB)

struct Smem {
    float W1s[DIMK * DIMK];   // 16 KB
    float e1v[NN * DIMK];     // 4 KB
    float xbuf[NN * DIMK];    // 4 KB
    float userv[DIMK];
    float e0v[DIMK];
    float x0[DIMK];
    float x1[DIMK];
    float outf[DIMK];
    float b0[DIMK];
    float b1[DIMK];
    float urel[NRELS + 3];
    float attn[NN * NN];
    float attn0[NN];
    int   e2[NN * NN];
    int   r2[NN * NN];
    int   r1[NN];
};

__device__ __forceinline__ float fsigmoid(float x) {
    return __fdividef(1.0f, 1.0f + __expf(-x));
}

__global__ __launch_bounds__(NT, 6)
void kgnn_kernel(const int* __restrict__ u, const int* __restrict__ v,
                 const int* __restrict__ adj, const int* __restrict__ rel_adj,
                 const float* __restrict__ usr_emb, const float* __restrict__ ent_emb,
                 const float* __restrict__ rel_emb,
                 const float* __restrict__ W0g, const float* __restrict__ b0g,
                 const float* __restrict__ W1g, const float* __restrict__ b1g,
                 float* __restrict__ out)
{
    extern __shared__ char smem_raw[];
    Smem& s = *reinterpret_cast<Smem*>(smem_raw);
    const int tid  = threadIdx.x;
    const int lane = tid & 31;
    const int warp = tid >> 5;
    const int c     = warp * 8 + (lane & 7);  // output column 0..63
    const int kh    = lane >> 3;              // k-quarter 0..3
    const int kbase = kh * 16;
    const bool kh0  = (kh == 0);

    const float4* ent4 = reinterpret_cast<const float4*>(ent_emb);

    // W0 column-slice in registers; W1 into smem; biases
    float Wreg[16];
    #pragma unroll
    for (int kk = 0; kk < 16; ++kk)
        Wreg[kk] = __ldg(W0g + (kbase + kk) * DIMK + c);
    {
        const float4* w1 = reinterpret_cast<const float4*>(W1g);
        float4* w1s = reinterpret_cast<float4*>(s.W1s);
        #pragma unroll
        for (int i = 0; i < 4; ++i) w1s[tid + i * NT] = __ldg(w1 + tid + i * NT);
        if (tid < DIMK) { s.b0[tid] = b0g[tid]; s.b1[tid] = b1g[tid]; }
    }

    for (int it = 0; it < IPB; ++it) {
        const int item = blockIdx.x * IPB + it;
        __syncthreads();

        // ---- P1: indices + e1v gather + root vectors + urel ----
        const int vv = __ldg(v + item);
        const int uu = __ldg(u + item);
        {
            const int m = tid >> 4, n = tid & 15;
            const int e1m = __ldg(adj + vv * NN + m);
            s.e2[tid] = __ldg(adj + e1m * NN + n);
            s.r2[tid] = __ldg(rel_adj + e1m * NN + n);
            reinterpret_cast<float4*>(s.e1v)[tid] = __ldg(ent4 + e1m * 16 + n);
            if (tid < 16) {
                s.r1[tid] = __ldg(rel_adj + vv * NN + tid);
                reinterpret_cast<float4*>(s.userv)[tid] = __ldg(
                    reinterpret_cast<const float4*>(usr_emb) + uu * 16 + tid);
            } else if (tid < 32) {
                reinterpret_cast<float4*>(s.e0v)[tid - 16] = __ldg(ent4 + vv * 16 + (tid - 16));
            }
            for (int r = warp; r < NRELS; r += 8) {
                float p = __ldg(usr_emb + uu * DIMK + lane) * __ldg(rel_emb + r * DIMK + lane)
                        + __ldg(usr_emb + uu * DIMK + lane + 32) * __ldg(rel_emb + r * DIMK + lane + 32);
                #pragma unroll
                for (int off = 16; off > 0; off >>= 1)
                    p += __shfl_xor_sync(0xffffffffu, p, off);
                if (lane == 0) s.urel[r] = p;
            }
        }
        __syncthreads();

        // ---- P2: softmax via half-warp butterflies (1 score per thread) ----
        {
            float sc = s.urel[s.r2[tid]];
            float mx = sc;
            #pragma unroll
            for (int off = 8; off > 0; off >>= 1)
                mx = fmaxf(mx, __shfl_xor_sync(0xffffffffu, mx, off));
            float e = __expf(sc - mx);
            float sum = e;
            #pragma unroll
            for (int off = 8; off > 0; off >>= 1)
                sum += __shfl_xor_sync(0xffffffffu, sum, off);
            s.attn[tid] = __fdividef(e, sum);

            if (warp == 0) {   // hop-0 softmax (both halves compute; lanes<16 write)
                float sc0 = s.urel[s.r1[lane & 15]];
                float m0 = sc0;
                #pragma unroll
                for (int off = 8; off > 0; off >>= 1)
                    m0 = fmaxf(m0, __shfl_xor_sync(0xffffffffu, m0, off));
                float e0 = __expf(sc0 - m0);
                float s0 = e0;
                #pragma unroll
                for (int off = 8; off > 0; off >>= 1)
                    s0 += __shfl_xor_sync(0xffffffffu, s0, off);
                if (lane < 16) s.attn0[lane] = __fdividef(e0, s0);
            }
        }
        __syncthreads();

        // ---- P3: hop-1 aggregation (float4 gather) + hop-0 aggregation ----
        {
            const int m  = warp * 2 + (lane >> 4);
            const int l4 = lane & 15;
            const int*   e2row = s.e2   + m * NN;
            const float* arow  = s.attn + m * NN;
            float4 acc = reinterpret_cast<const float4*>(s.e1v + m * DIMK)[l4];
            #pragma unroll
            for (int n = 0; n < NN; ++n) {
                const float4 vv4 = __ldg(ent4 + e2row[n] * 16 + l4);
                const float  an  = arow[n];
                acc.x = fmaf(an, vv4.x, acc.x);
                acc.y = fmaf(an, vv4.y, acc.y);
                acc.z = fmaf(an, vv4.z, acc.z);
                acc.w = fmaf(an, vv4.w, acc.w);
            }
            reinterpret_cast<float4*>(s.xbuf + m * DIMK)[l4] = acc;

            if (tid < 16) {
                float4 a0 = reinterpret_cast<const float4*>(s.e0v)[tid];
                #pragma unroll
                for (int n = 0; n < NN; ++n) {
                    const float4 ev = reinterpret_cast<const float4*>(s.e1v + n * DIMK)[tid];
                    const float  an = s.attn0[n];
                    a0.x = fmaf(an, ev.x, a0.x);
                    a0.y = fmaf(an, ev.y, a0.y);
                    a0.z = fmaf(an, ev.z, a0.z);
                    a0.w = fmaf(an, ev.w, a0.w);
                }
                reinterpret_cast<float4*>(s.x0)[tid] = a0;
            }
        }
        __syncthreads();

        // ---- P4: fused GEMM. h1 never hits smem: x1 accumulated in-register ----
        {
            // out0 = sigmoid(x0 @ W0 + b0)  (kh0 lanes hold result)
            float a16 = 0.f;
            #pragma unroll
            for (int q = 0; q < 4; ++q) {
                const float4 xv = *reinterpret_cast<const float4*>(s.x0 + kbase + q * 4);
                a16 = fmaf(xv.x, Wreg[q * 4 + 0], a16);
                a16 = fmaf(xv.y, Wreg[q * 4 + 1], a16);
                a16 = fmaf(xv.z, Wreg[q * 4 + 2], a16);
                a16 = fmaf(xv.w, Wreg[q * 4 + 3], a16);
            }
            a16 += __shfl_xor_sync(0xffffffffu, a16, 8);
            a16 += __shfl_xor_sync(0xffffffffu, a16, 16);
            float x1acc = kh0 ? fsigmoid(a16 + s.b0[c]) : 0.f;

            #pragma unroll
            for (int r = 0; r < NN; ++r) {
                float a = 0.f;
                #pragma unroll
                for (int q = 0; q < 4; ++q) {
                    const float4 xv = *reinterpret_cast<const float4*>(
                        s.xbuf + r * DIMK + kbase + q * 4);
                    a = fmaf(xv.x, Wreg[q * 4 + 0], a);
                    a = fmaf(xv.y, Wreg[q * 4 + 1], a);
                    a = fmaf(xv.z, Wreg[q * 4 + 2], a);
                    a = fmaf(xv.w, Wreg[q * 4 + 3], a);
                }
                a += __shfl_xor_sync(0xffffffffu, a, 8);
                a += __shfl_xor_sync(0xffffffffu, a, 16);
                if (kh0) {
                    const float h = fsigmoid(a + s.b0[c]);
                    x1acc = fmaf(s.attn0[r], h, x1acc);
                }
            }
            if (kh0) s.x1[c] = x1acc;
        }
        __syncthreads();

        // ---- P6: final GEMM (W1 from smem) + tanh ----
        {
            float acc = 0.f;
            #pragma unroll
            for (int q = 0; q < 4; ++q) {
                const float4 xv = *reinterpret_cast<const float4*>(s.x1 + kbase + q * 4);
                acc = fmaf(xv.x, s.W1s[(kbase + q * 4 + 0) * DIMK + c], acc);
                acc = fmaf(xv.y, s.W1s[(kbase + q * 4 + 1) * DIMK + c], acc);
                acc = fmaf(xv.z, s.W1s[(kbase + q * 4 + 2) * DIMK + c], acc);
                acc = fmaf(xv.w, s.W1s[(kbase + q * 4 + 3) * DIMK + c], acc);
            }
            acc += __shfl_xor_sync(0xffffffffu, acc, 8);
            acc += __shfl_xor_sync(0xffffffffu, acc, 16);
            if (kh0) s.outf[c] = tanhf(acc + s.b1[c]);
        }
        __syncthreads();

        // ---- P7: sigmoid(user . item) ----
        if (tid < 32) {
            float p = s.userv[tid] * s.outf[tid] + s.userv[tid + 32] * s.outf[tid + 32];
            #pragma unroll
            for (int off = 16; off > 0; off >>= 1)
                p += __shfl_xor_sync(0xffffffffu, p, off);
            if (tid == 0) out[item] = fsigmoid(p);
        }
    }
}

extern "C" void kernel_launch(void* const* d_in, const int* in_sizes, int n_in,
                              void* d_out, int out_size) {
    const int*   u       = (const int*)d_in[0];
    const int*   v       = (const int*)d_in[1];
    const int*   adj     = (const int*)d_in[2];
    const int*   rel_adj = (const int*)d_in[3];
    const float* usr_emb = (const float*)d_in[4];
    const float* ent_emb = (const float*)d_in[5];
    const float* rel_emb = (const float*)d_in[6];
    const float* W0      = (const float*)d_in[7];
    const float* b0      = (const float*)d_in[8];
    const float* W1      = (const float*)d_in[9];
    const float* b1      = (const float*)d_in[10];
    float* outp = (float*)d_out;

    const int smem = (int)sizeof(Smem);
    cudaFuncSetAttribute(kgnn_kernel, cudaFuncAttributeMaxDynamicSharedMemorySize, smem);
    kgnn_kernel<<<GRID, NT, smem>>>(u, v, adj, rel_adj, usr_emb, ent_emb, rel_emb,
                                    W0, b0, W1, b1, outp);
}

// round 5
// speedup vs baseline: 1.2337x; 1.0237x over previous
#include <cuda_runtime.h>
#include <math.h>

#define DIMK 64
#define NN 16
#define BATCH 4096
#define NRELS 33
#define IPB 2
#define NT 256
#define GRID (BATCH / IPB)

struct Smem {
    float e1v[NN * DIMK];     // 4 KB
    float xbuf[NN * DIMK];    // 4 KB
    float userv[DIMK];
    float e0v[DIMK];
    float x0[DIMK];
    float x1[DIMK];
    float outf[DIMK];
    float b0[DIMK];
    float b1[DIMK];
    float attn[NN * NN];      // 1 KB
    float urel[NRELS + 3];
    float attn0[NN];
    int   e2[NN * NN];        // 1 KB
    int   r2[NN * NN];        // 1 KB
    int   r1[NN];
};

__device__ __forceinline__ float fsigmoid(float x) {
    return __fdividef(1.0f, 1.0f + __expf(-x));
}

__global__ __launch_bounds__(NT, 6)
void kgnn_kernel(const int* __restrict__ u, const int* __restrict__ v,
                 const int* __restrict__ adj, const int* __restrict__ rel_adj,
                 const float* __restrict__ usr_emb, const float* __restrict__ ent_emb,
                 const float* __restrict__ rel_emb,
                 const float* __restrict__ W0g, const float* __restrict__ b0g,
                 const float* __restrict__ W1g, const float* __restrict__ b1g,
                 float* __restrict__ out)
{
    extern __shared__ char smem_raw[];
    Smem& s = *reinterpret_cast<Smem*>(smem_raw);
    const int tid  = threadIdx.x;
    const int lane = tid & 31;
    const int warp = tid >> 5;
    const int c     = warp * 8 + (lane & 7);  // output column 0..63
    const int kh    = lane >> 3;              // k-quarter 0..3
    const int kbase = kh * 16;
    const bool kh0  = (kh == 0);

    const float4* ent4 = reinterpret_cast<const float4*>(ent_emb);

    // W0 column-slice in registers, once per CTA
    float Wreg[16];
    #pragma unroll
    for (int kk = 0; kk < 16; ++kk)
        Wreg[kk] = __ldg(W0g + (kbase + kk) * DIMK + c);
    if (tid < DIMK) { s.b0[tid] = b0g[tid]; s.b1[tid] = b1g[tid]; }

    for (int it = 0; it < IPB; ++it) {
        const int item = blockIdx.x * IPB + it;
        __syncthreads();

        // ---- P1: indices + e1v gather + root vectors + urel ----
        const int vv = __ldg(v + item);
        const int uu = __ldg(u + item);
        {
            const int m = tid >> 4, n = tid & 15;
            const int e1m = __ldg(adj + vv * NN + m);
            s.e2[tid] = __ldg(adj + e1m * NN + n);
            s.r2[tid] = __ldg(rel_adj + e1m * NN + n);
            reinterpret_cast<float4*>(s.e1v)[tid] = __ldg(ent4 + e1m * 16 + n);
            if (tid < 16) {
                s.r1[tid] = __ldg(rel_adj + vv * NN + tid);
                reinterpret_cast<float4*>(s.userv)[tid] = __ldg(
                    reinterpret_cast<const float4*>(usr_emb) + uu * 16 + tid);
            } else if (tid < 32) {
                reinterpret_cast<float4*>(s.e0v)[tid - 16] = __ldg(ent4 + vv * 16 + (tid - 16));
            }
            for (int r = warp; r < NRELS; r += 8) {
                float p = __ldg(usr_emb + uu * DIMK + lane) * __ldg(rel_emb + r * DIMK + lane)
                        + __ldg(usr_emb + uu * DIMK + lane + 32) * __ldg(rel_emb + r * DIMK + lane + 32);
                #pragma unroll
                for (int off = 16; off > 0; off >>= 1)
                    p += __shfl_xor_sync(0xffffffffu, p, off);
                if (lane == 0) s.urel[r] = p;
            }
        }
        __syncthreads();

        // ---- P2: softmax via half-warp butterflies ----
        {
            float sc = s.urel[s.r2[tid]];
            float mx = sc;
            #pragma unroll
            for (int off = 8; off > 0; off >>= 1)
                mx = fmaxf(mx, __shfl_xor_sync(0xffffffffu, mx, off));
            float e = __expf(sc - mx);
            float sum = e;
            #pragma unroll
            for (int off = 8; off > 0; off >>= 1)
                sum += __shfl_xor_sync(0xffffffffu, sum, off);
            s.attn[tid] = __fdividef(e, sum);

            if (warp == 0) {
                float sc0 = s.urel[s.r1[lane & 15]];
                float m0 = sc0;
                #pragma unroll
                for (int off = 8; off > 0; off >>= 1)
                    m0 = fmaxf(m0, __shfl_xor_sync(0xffffffffu, m0, off));
                float e0 = __expf(sc0 - m0);
                float s0 = e0;
                #pragma unroll
                for (int off = 8; off > 0; off >>= 1)
                    s0 += __shfl_xor_sync(0xffffffffu, s0, off);
                if (lane < 16) s.attn0[lane] = __fdividef(e0, s0);
            }
        }
        __syncthreads();

        // ---- P3: hop-1 aggregation (regs-resident idx/attn, float4 gather) ----
        {
            const int m  = warp * 2 + (lane >> 4);
            const int l4 = lane & 15;
            const int4*   e2v = reinterpret_cast<const int4*>(s.e2 + m * NN);
            const float4* av  = reinterpret_cast<const float4*>(s.attn + m * NN);
            float4 acc = reinterpret_cast<const float4*>(s.e1v + m * DIMK)[l4];
            #pragma unroll
            for (int j = 0; j < 4; ++j) {
                const int4   ei = e2v[j];
                const float4 aw = av[j];
                const float4 v0 = __ldg(ent4 + ei.x * 16 + l4);
                const float4 v1 = __ldg(ent4 + ei.y * 16 + l4);
                const float4 v2 = __ldg(ent4 + ei.z * 16 + l4);
                const float4 v3 = __ldg(ent4 + ei.w * 16 + l4);
                acc.x = fmaf(aw.x, v0.x, acc.x); acc.y = fmaf(aw.x, v0.y, acc.y);
                acc.z = fmaf(aw.x, v0.z, acc.z); acc.w = fmaf(aw.x, v0.w, acc.w);
                acc.x = fmaf(aw.y, v1.x, acc.x); acc.y = fmaf(aw.y, v1.y, acc.y);
                acc.z = fmaf(aw.y, v1.z, acc.z); acc.w = fmaf(aw.y, v1.w, acc.w);
                acc.x = fmaf(aw.z, v2.x, acc.x); acc.y = fmaf(aw.z, v2.y, acc.y);
                acc.z = fmaf(aw.z, v2.z, acc.z); acc.w = fmaf(aw.z, v2.w, acc.w);
                acc.x = fmaf(aw.w, v3.x, acc.x); acc.y = fmaf(aw.w, v3.y, acc.y);
                acc.z = fmaf(aw.w, v3.z, acc.z); acc.w = fmaf(aw.w, v3.w, acc.w);
            }
            reinterpret_cast<float4*>(s.xbuf + m * DIMK)[l4] = acc;

            if (tid < 16) {
                float4 a0 = reinterpret_cast<const float4*>(s.e0v)[tid];
                #pragma unroll
                for (int n = 0; n < NN; ++n) {
                    const float4 ev = reinterpret_cast<const float4*>(s.e1v + n * DIMK)[tid];
                    const float  an = s.attn0[n];
                    a0.x = fmaf(an, ev.x, a0.x);
                    a0.y = fmaf(an, ev.y, a0.y);
                    a0.z = fmaf(an, ev.z, a0.z);
                    a0.w = fmaf(an, ev.w, a0.w);
                }
                reinterpret_cast<float4*>(s.x0)[tid] = a0;
            }
        }
        __syncthreads();

        // ---- P4: fused GEMM (row pairs for ILP; x1 accumulated in-register) ----
        {
            const float b0c = s.b0[c];
            float x1acc = 0.f;
            #pragma unroll
            for (int r = 0; r < NN; r += 2) {
                float a0 = 0.f, a1 = 0.f;
                #pragma unroll
                for (int q = 0; q < 4; ++q) {
                    const float4 xv0 = *reinterpret_cast<const float4*>(
                        s.xbuf + r * DIMK + kbase + q * 4);
                    const float4 xv1 = *reinterpret_cast<const float4*>(
                        s.xbuf + (r + 1) * DIMK + kbase + q * 4);
                    a0 = fmaf(xv0.x, Wreg[q * 4 + 0], a0);
                    a1 = fmaf(xv1.x, Wreg[q * 4 + 0], a1);
                    a0 = fmaf(xv0.y, Wreg[q * 4 + 1], a0);
                    a1 = fmaf(xv1.y, Wreg[q * 4 + 1], a1);
                    a0 = fmaf(xv0.z, Wreg[q * 4 + 2], a0);
                    a1 = fmaf(xv1.z, Wreg[q * 4 + 2], a1);
                    a0 = fmaf(xv0.w, Wreg[q * 4 + 3], a0);
                    a1 = fmaf(xv1.w, Wreg[q * 4 + 3], a1);
                }
                a0 += __shfl_xor_sync(0xffffffffu, a0, 8);
                a1 += __shfl_xor_sync(0xffffffffu, a1, 8);
                a0 += __shfl_xor_sync(0xffffffffu, a0, 16);
                a1 += __shfl_xor_sync(0xffffffffu, a1, 16);
                if (kh0) {
                    x1acc = fmaf(s.attn0[r],     fsigmoid(a0 + b0c), x1acc);
                    x1acc = fmaf(s.attn0[r + 1], fsigmoid(a1 + b0c), x1acc);
                }
            }
            // x0 row -> out0 folded into x1
            float a16 = 0.f;
            #pragma unroll
            for (int q = 0; q < 4; ++q) {
                const float4 xv = *reinterpret_cast<const float4*>(s.x0 + kbase + q * 4);
                a16 = fmaf(xv.x, Wreg[q * 4 + 0], a16);
                a16 = fmaf(xv.y, Wreg[q * 4 + 1], a16);
                a16 = fmaf(xv.z, Wreg[q * 4 + 2], a16);
                a16 = fmaf(xv.w, Wreg[q * 4 + 3], a16);
            }
            a16 += __shfl_xor_sync(0xffffffffu, a16, 8);
            a16 += __shfl_xor_sync(0xffffffffu, a16, 16);
            if (kh0) s.x1[c] = x1acc + fsigmoid(a16 + b0c);
        }
        __syncthreads();

        // ---- P5: final GEMM (W1 via L1-cached ldg) + tanh ----
        {
            float acc = 0.f;
            #pragma unroll
            for (int kk = 0; kk < 16; ++kk) {
                const int k = kbase + kk;
                acc = fmaf(s.x1[k], __ldg(W1g + k * DIMK + c), acc);
            }
            acc += __shfl_xor_sync(0xffffffffu, acc, 8);
            acc += __shfl_xor_sync(0xffffffffu, acc, 16);
            if (kh0) s.outf[c] = tanhf(acc + s.b1[c]);
        }
        __syncthreads();

        // ---- P6: sigmoid(user . item) ----
        if (tid < 32) {
            float p = s.userv[tid] * s.outf[tid] + s.userv[tid + 32] * s.outf[tid + 32];
            #pragma unroll
            for (int off = 16; off > 0; off >>= 1)
                p += __shfl_xor_sync(0xffffffffu, p, off);
            if (tid == 0) out[item] = fsigmoid(p);
        }
    }
}

extern "C" void kernel_launch(void* const* d_in, const int* in_sizes, int n_in,
                              void* d_out, int out_size) {
    const int*   u       = (const int*)d_in[0];
    const int*   v       = (const int*)d_in[1];
    const int*   adj     = (const int*)d_in[2];
    const int*   rel_adj = (const int*)d_in[3];
    const float* usr_emb = (const float*)d_in[4];
    const float* ent_emb = (const float*)d_in[5];
    const float* rel_emb = (const float*)d_in[6];
    const float* W0      = (const float*)d_in[7];
    const float* b0      = (const float*)d_in[8];
    const float* W1      = (const float*)d_in[9];
    const float* b1      = (const float*)d_in[10];
    float* outp = (float*)d_out;

    const int smem = (int)sizeof(Smem);
    cudaFuncSetAttribute(kgnn_kernel, cudaFuncAttributeMaxDynamicSharedMemorySize, smem);
    kgnn_kernel<<<GRID, NT, smem>>>(u, v, adj, rel_adj, usr_emb, ent_emb, rel_emb,
                                    W0, b0, W1, b1, outp);
}

// round 6
// speedup vs baseline: 1.6163x; 1.3101x over previous
#include <cuda_runtime.h>
#include <math.h>

#define DIMK 64
#define NN 16
#define BATCH 4096
#define NRELS 33
#define NT 256
#define NITEMS 2
#define GRID (BATCH / NITEMS)

struct PerItem {
    float e1v[NN * DIMK];     // 4 KB
    float xbuf[NN * DIMK];    // 4 KB
    float userv[DIMK];
    float e0v[DIMK];
    float x0[DIMK];
    float x1[DIMK];
    float outf[DIMK];
    float attn[NN * NN];      // 1 KB
    float urel[NRELS + 3];
    float attn0[NN];
    int   e2[NN * NN];        // 1 KB
    int   r2[NN * NN];        // 1 KB
    int   r1[NN];
};

struct Smem {
    PerItem pi[NITEMS];
    float b0[DIMK];
    float b1[DIMK];
};

__device__ __forceinline__ float fsigmoid(float x) {
    return __fdividef(1.0f, 1.0f + __expf(-x));
}

__global__ __launch_bounds__(NT, 6)
void kgnn_kernel(const int* __restrict__ u, const int* __restrict__ v,
                 const int* __restrict__ adj, const int* __restrict__ rel_adj,
                 const float* __restrict__ usr_emb, const float* __restrict__ ent_emb,
                 const float* __restrict__ rel_emb,
                 const float* __restrict__ W0g, const float* __restrict__ b0g,
                 const float* __restrict__ W1g, const float* __restrict__ b1g,
                 float* __restrict__ out)
{
    extern __shared__ char smem_raw[];
    Smem& s = *reinterpret_cast<Smem*>(smem_raw);
    const int tid  = threadIdx.x;
    const int lane = tid & 31;
    const int warp = tid >> 5;
    const int c     = warp * 8 + (lane & 7);  // output column 0..63
    const int kh    = lane >> 3;              // k-quarter 0..3
    const int kbase = kh * 16;
    const bool kh0  = (kh == 0);

    const float4* ent4 = reinterpret_cast<const float4*>(ent_emb);
    const int item0 = blockIdx.x * NITEMS;

    // W0 column-slice in registers, once per CTA
    float Wreg[16];
    #pragma unroll
    for (int kk = 0; kk < 16; ++kk)
        Wreg[kk] = __ldg(W0g + (kbase + kk) * DIMK + c);
    if (tid < DIMK) { s.b0[tid] = b0g[tid]; s.b1[tid] = b1g[tid]; }
    __syncthreads();

    // ---- P1: indices + e1v gather + root vectors + urel (both items) ----
    #pragma unroll
    for (int ii = 0; ii < NITEMS; ++ii) {
        PerItem& p = s.pi[ii];
        const int vv = __ldg(v + item0 + ii);
        const int uu = __ldg(u + item0 + ii);
        const int m = tid >> 4, n = tid & 15;
        const int e1m = __ldg(adj + vv * NN + m);
        p.e2[tid] = __ldg(adj + e1m * NN + n);
        p.r2[tid] = __ldg(rel_adj + e1m * NN + n);
        reinterpret_cast<float4*>(p.e1v)[tid] = __ldg(ent4 + e1m * 16 + n);
        if (tid < 16) {
            p.r1[tid] = __ldg(rel_adj + vv * NN + tid);
            reinterpret_cast<float4*>(p.userv)[tid] = __ldg(
                reinterpret_cast<const float4*>(usr_emb) + uu * 16 + tid);
        } else if (tid < 32) {
            reinterpret_cast<float4*>(p.e0v)[tid - 16] = __ldg(ent4 + vv * 16 + (tid - 16));
        }
        const float ua = __ldg(usr_emb + uu * DIMK + lane);
        const float ub = __ldg(usr_emb + uu * DIMK + lane + 32);
        for (int r = warp; r < NRELS; r += 8) {
            float pp = ua * __ldg(rel_emb + r * DIMK + lane)
                     + ub * __ldg(rel_emb + r * DIMK + lane + 32);
            #pragma unroll
            for (int off = 16; off > 0; off >>= 1)
                pp += __shfl_xor_sync(0xffffffffu, pp, off);
            if (lane == 0) p.urel[r] = pp;
        }
    }
    __syncthreads();

    // ---- P2: softmax via half-warp butterflies (both items) ----
    #pragma unroll
    for (int ii = 0; ii < NITEMS; ++ii) {
        PerItem& p = s.pi[ii];
        float sc = p.urel[p.r2[tid]];
        float mx = sc;
        #pragma unroll
        for (int off = 8; off > 0; off >>= 1)
            mx = fmaxf(mx, __shfl_xor_sync(0xffffffffu, mx, off));
        float e = __expf(sc - mx);
        float sum = e;
        #pragma unroll
        for (int off = 8; off > 0; off >>= 1)
            sum += __shfl_xor_sync(0xffffffffu, sum, off);
        p.attn[tid] = __fdividef(e, sum);

        if (warp == ii) {   // hop-0 softmax on warp ii
            float sc0 = p.urel[p.r1[lane & 15]];
            float m0 = sc0;
            #pragma unroll
            for (int off = 8; off > 0; off >>= 1)
                m0 = fmaxf(m0, __shfl_xor_sync(0xffffffffu, m0, off));
            float e0 = __expf(sc0 - m0);
            float s0 = e0;
            #pragma unroll
            for (int off = 8; off > 0; off >>= 1)
                s0 += __shfl_xor_sync(0xffffffffu, s0, off);
            if (lane < 16) p.attn0[lane] = __fdividef(e0, s0);
        }
    }
    __syncthreads();

    // ---- P3: hop-1 aggregation (both items) + x0 on warps 6/7 ----
    #pragma unroll
    for (int ii = 0; ii < NITEMS; ++ii) {
        PerItem& p = s.pi[ii];
        const int m  = warp * 2 + (lane >> 4);
        const int l4 = lane & 15;
        const int4*   e2v = reinterpret_cast<const int4*>(p.e2 + m * NN);
        const float4* av  = reinterpret_cast<const float4*>(p.attn + m * NN);
        float4 acc = reinterpret_cast<const float4*>(p.e1v + m * DIMK)[l4];
        #pragma unroll
        for (int j = 0; j < 4; ++j) {
            const int4   ei = e2v[j];
            const float4 aw = av[j];
            const float4 v0 = __ldg(ent4 + ei.x * 16 + l4);
            const float4 v1 = __ldg(ent4 + ei.y * 16 + l4);
            const float4 v2 = __ldg(ent4 + ei.z * 16 + l4);
            const float4 v3 = __ldg(ent4 + ei.w * 16 + l4);
            acc.x = fmaf(aw.x, v0.x, acc.x); acc.y = fmaf(aw.x, v0.y, acc.y);
            acc.z = fmaf(aw.x, v0.z, acc.z); acc.w = fmaf(aw.x, v0.w, acc.w);
            acc.x = fmaf(aw.y, v1.x, acc.x); acc.y = fmaf(aw.y, v1.y, acc.y);
            acc.z = fmaf(aw.y, v1.z, acc.z); acc.w = fmaf(aw.y, v1.w, acc.w);
            acc.x = fmaf(aw.z, v2.x, acc.x); acc.y = fmaf(aw.z, v2.y, acc.y);
            acc.z = fmaf(aw.z, v2.z, acc.z); acc.w = fmaf(aw.z, v2.w, acc.w);
            acc.x = fmaf(aw.w, v3.x, acc.x); acc.y = fmaf(aw.w, v3.y, acc.y);
            acc.z = fmaf(aw.w, v3.z, acc.z); acc.w = fmaf(aw.w, v3.w, acc.w);
        }
        reinterpret_cast<float4*>(p.xbuf + m * DIMK)[l4] = acc;

        if (warp == 6 + ii && lane < 16) {   // x0 aggregation, one warp per item
            float4 a0 = reinterpret_cast<const float4*>(p.e0v)[lane];
            #pragma unroll
            for (int n = 0; n < NN; ++n) {
                const float4 ev = reinterpret_cast<const float4*>(p.e1v + n * DIMK)[lane];
                const float  an = p.attn0[n];
                a0.x = fmaf(an, ev.x, a0.x);
                a0.y = fmaf(an, ev.y, a0.y);
                a0.z = fmaf(an, ev.z, a0.z);
                a0.w = fmaf(an, ev.w, a0.w);
            }
            reinterpret_cast<float4*>(p.x0)[lane] = a0;
        }
    }
    __syncthreads();

    // ---- P4: fused GEMM (both items; h1 stays in registers) ----
    #pragma unroll
    for (int ii = 0; ii < NITEMS; ++ii) {
        PerItem& p = s.pi[ii];
        const float b0c = s.b0[c];
        float x1acc = 0.f;
        #pragma unroll
        for (int r = 0; r < NN; r += 2) {
            float a0 = 0.f, a1 = 0.f;
            #pragma unroll
            for (int q = 0; q < 4; ++q) {
                const float4 xv0 = *reinterpret_cast<const float4*>(
                    p.xbuf + r * DIMK + kbase + q * 4);
                const float4 xv1 = *reinterpret_cast<const float4*>(
                    p.xbuf + (r + 1) * DIMK + kbase + q * 4);
                a0 = fmaf(xv0.x, Wreg[q * 4 + 0], a0);
                a1 = fmaf(xv1.x, Wreg[q * 4 + 0], a1);
                a0 = fmaf(xv0.y, Wreg[q * 4 + 1], a0);
                a1 = fmaf(xv1.y, Wreg[q * 4 + 1], a1);
                a0 = fmaf(xv0.z, Wreg[q * 4 + 2], a0);
                a1 = fmaf(xv1.z, Wreg[q * 4 + 2], a1);
                a0 = fmaf(xv0.w, Wreg[q * 4 + 3], a0);
                a1 = fmaf(xv1.w, Wreg[q * 4 + 3], a1);
            }
            a0 += __shfl_xor_sync(0xffffffffu, a0, 8);
            a1 += __shfl_xor_sync(0xffffffffu, a1, 8);
            a0 += __shfl_xor_sync(0xffffffffu, a0, 16);
            a1 += __shfl_xor_sync(0xffffffffu, a1, 16);
            if (kh0) {
                x1acc = fmaf(p.attn0[r],     fsigmoid(a0 + b0c), x1acc);
                x1acc = fmaf(p.attn0[r + 1], fsigmoid(a1 + b0c), x1acc);
            }
        }
        float a16 = 0.f;
        #pragma unroll
        for (int q = 0; q < 4; ++q) {
            const float4 xv = *reinterpret_cast<const float4*>(p.x0 + kbase + q * 4);
            a16 = fmaf(xv.x, Wreg[q * 4 + 0], a16);
            a16 = fmaf(xv.y, Wreg[q * 4 + 1], a16);
            a16 = fmaf(xv.z, Wreg[q * 4 + 2], a16);
            a16 = fmaf(xv.w, Wreg[q * 4 + 3], a16);
        }
        a16 += __shfl_xor_sync(0xffffffffu, a16, 8);
        a16 += __shfl_xor_sync(0xffffffffu, a16, 16);
        if (kh0) p.x1[c] = x1acc + fsigmoid(a16 + b0c);
    }
    __syncthreads();

    // ---- P5: final GEMM (W1 via L1-cached ldg) + tanh (both items) ----
    #pragma unroll
    for (int ii = 0; ii < NITEMS; ++ii) {
        PerItem& p = s.pi[ii];
        float acc = 0.f;
        #pragma unroll
        for (int kk = 0; kk < 16; ++kk) {
            const int k = kbase + kk;
            acc = fmaf(p.x1[k], __ldg(W1g + k * DIMK + c), acc);
        }
        acc += __shfl_xor_sync(0xffffffffu, acc, 8);
        acc += __shfl_xor_sync(0xffffffffu, acc, 16);
        if (kh0) p.outf[c] = tanhf(acc + s.b1[c]);
    }
    __syncthreads();

    // ---- P6: sigmoid(user . item), one warp per item ----
    if (warp < NITEMS) {
        PerItem& p = s.pi[warp];
        float pp = p.userv[lane] * p.outf[lane] + p.userv[lane + 32] * p.outf[lane + 32];
        #pragma unroll
        for (int off = 16; off > 0; off >>= 1)
            pp += __shfl_xor_sync(0xffffffffu, pp, off);
        if (lane == 0) out[item0 + warp] = fsigmoid(pp);
    }
}

extern "C" void kernel_launch(void* const* d_in, const int* in_sizes, int n_in,
                              void* d_out, int out_size) {
    const int*   u       = (const int*)d_in[0];
    const int*   v       = (const int*)d_in[1];
    const int*   adj     = (const int*)d_in[2];
    const int*   rel_adj = (const int*)d_in[3];
    const float* usr_emb = (const float*)d_in[4];
    const float* ent_emb = (const float*)d_in[5];
    const float* rel_emb = (const float*)d_in[6];
    const float* W0      = (const float*)d_in[7];
    const float* b0      = (const float*)d_in[8];
    const float* W1      = (const float*)d_in[9];
    const float* b1      = (const float*)d_in[10];
    float* outp = (float*)d_out;

    const int smem = (int)sizeof(Smem);
    cudaFuncSetAttribute(kgnn_kernel, cudaFuncAttributeMaxDynamicSharedMemorySize, smem);
    kgnn_kernel<<<GRID, NT, smem>>>(u, v, adj, rel_adj, usr_emb, ent_emb, rel_emb,
                                    W0, b0, W1, b1, outp);
}